// round 8
// baseline (speedup 1.0000x reference)
#include <cuda_runtime.h>
#include <cuda_bf16.h>
#include <cstdint>

// Problem constants
#define NJ 52
#define NB 32
#define KP 64            // K padded (bf16 row = 128 B = SW128 atom)
#define MT 128           // vertices per CTA (GEMM M tile)
#define NTOT 384         // 32 batches * 12 elements, n = b*12 + e
#define THREADS 256      // 8 warps: 4 (M) x 2 (N)
#define NCHUNK 4         // N chunks of 96 cols (8 batches each)
#define CPAD 100         // C smem row stride in floats (25 segs, coprime 8)

// SMEM byte offsets (dynamic)
#define S_AHI 0
#define S_ALO (S_AHI + MT * 128)          // 16384
#define S_BHI (S_ALO + MT * 128)          // 32768
#define S_BLO (S_BHI + NTOT * 128)        // 81920
#define S_C   (S_BLO + NTOT * 128)        // 131072
#define S_TOTAL (S_C + MT * CPAD * 4)     // 182272

#define SW128(b) ((b) ^ (((b) >> 3) & 0x70))

__device__ __forceinline__ uint32_t smem_u32(const void* p) {
    uint32_t a;
    asm("{ .reg .u64 t; cvta.to.shared.u64 t, %1; cvt.u32.u64 %0, t; }"
        : "=r"(a) : "l"(p));
    return a;
}

__device__ __forceinline__ void ldsm_x4(uint32_t* d, uint32_t addr) {
    asm volatile("ldmatrix.sync.aligned.m8n8.x4.shared.b16 {%0,%1,%2,%3}, [%4];"
                 : "=r"(d[0]), "=r"(d[1]), "=r"(d[2]), "=r"(d[3]) : "r"(addr));
}

__device__ __forceinline__ void ldsm_x2(uint32_t& d0, uint32_t& d1, uint32_t addr) {
    asm volatile("ldmatrix.sync.aligned.m8n8.x2.shared.b16 {%0,%1}, [%2];"
                 : "=r"(d0), "=r"(d1) : "r"(addr));
}

__device__ __forceinline__ void mma_bf16(float* c, const uint32_t* a,
                                         uint32_t b0, uint32_t b1) {
    asm volatile(
        "mma.sync.aligned.m16n8k16.row.col.f32.bf16.bf16.f32 "
        "{%0,%1,%2,%3}, {%4,%5,%6,%7}, {%8,%9}, {%0,%1,%2,%3};"
        : "+f"(c[0]), "+f"(c[1]), "+f"(c[2]), "+f"(c[3])
        : "r"(a[0]), "r"(a[1]), "r"(a[2]), "r"(a[3]), "r"(b0), "r"(b1));
}

__device__ __forceinline__ void split_bf16(float x, __nv_bfloat16& hi, __nv_bfloat16& lo) {
    hi = __float2bfloat16(x);
    lo = __float2bfloat16(x - __bfloat162float(hi));
}

__global__ void __launch_bounds__(THREADS)
skin_mma_kernel(const float* __restrict__ verts,   // [V,3]
                const float* __restrict__ W,       // [V,NJ]
                const float* __restrict__ M,       // [NB,NJ,4,4]
                float* __restrict__ out,           // [NB,V,3]
                int V) {
    extern __shared__ char smem[];
    const uint32_t sb = smem_u32(smem);
    const int tid = threadIdx.x;
    const int lane = tid & 31;
    const int wid = tid >> 5;
    const int warp_m = wid >> 1;     // 0..3 -> rows 32*warp_m
    const int warp_n = wid & 1;      // 0..1 -> chunk-local cols 48*warp_n
    const int vbase = blockIdx.x * MT;

    // ---- Fill A: weights of 128 vertices, bf16 hi/lo, SW128 rows of 128B ----
    if (tid < MT) {
        const int r = tid;
        int vv = vbase + r;
        if (vv >= V) vv = V - 1;
        float w[NJ];
        const float4* wp = reinterpret_cast<const float4*>(W + (size_t)vv * NJ);
        #pragma unroll
        for (int q = 0; q < NJ / 4; q++) {
            float4 t = wp[q];
            w[4 * q] = t.x; w[4 * q + 1] = t.y; w[4 * q + 2] = t.z; w[4 * q + 3] = t.w;
        }
        #pragma unroll
        for (int jp = 0; jp < KP / 2; jp++) {
            float w0 = (2 * jp < NJ) ? w[2 * jp] : 0.0f;
            float w1 = (2 * jp + 1 < NJ) ? w[2 * jp + 1] : 0.0f;
            __nv_bfloat16 h0, l0, h1, l1;
            split_bf16(w0, h0, l0);
            split_bf16(w1, h1, l1);
            uint32_t off = SW128((uint32_t)(r * 128 + jp * 4));
            __nv_bfloat162 hp; hp.x = h0; hp.y = h1;
            __nv_bfloat162 lp; lp.x = l0; lp.y = l1;
            *reinterpret_cast<__nv_bfloat162*>(smem + S_AHI + off) = hp;
            *reinterpret_cast<__nv_bfloat162*>(smem + S_ALO + off) = lp;
        }
    }

    // ---- Fill B: B[n][k] = M[b, j=k, e], n = b*12 + e; bf16 hi/lo ----
    for (int idx = tid; idx < NTOT * (KP / 2); idx += THREADS) {
        const int n = idx >> 5;
        const int jp = idx & 31;
        const int b = n / 12;
        const int e = n - b * 12;
        const int j0 = 2 * jp, j1 = 2 * jp + 1;
        float m0 = (j0 < NJ) ? M[((size_t)b * NJ + j0) * 16 + e] : 0.0f;
        float m1 = (j1 < NJ) ? M[((size_t)b * NJ + j1) * 16 + e] : 0.0f;
        __nv_bfloat16 h0, l0, h1, l1;
        split_bf16(m0, h0, l0);
        split_bf16(m1, h1, l1);
        uint32_t off = SW128((uint32_t)(n * 128 + jp * 4));
        __nv_bfloat162 hp; hp.x = h0; hp.y = h1;
        __nv_bfloat162 lp; lp.x = l0; lp.y = l1;
        *reinterpret_cast<__nv_bfloat162*>(smem + S_BHI + off) = hp;
        *reinterpret_cast<__nv_bfloat162*>(smem + S_BLO + off) = lp;
    }
    __syncthreads();

    // ---- Load A fragments once (hi and lo): 2 m-tiles x 4 k-tiles ----
    uint32_t ah[2][4][4], al[2][4][4];
    {
        const int sub = lane >> 3;       // 0..3 quadrant
        const int rin = lane & 7;
        #pragma unroll
        for (int mt = 0; mt < 2; mt++) {
            #pragma unroll
            for (int kt = 0; kt < 4; kt++) {
                const int row = warp_m * 32 + mt * 16 + rin + (sub & 1) * 8;
                const uint32_t byte = (uint32_t)(row * 128 + kt * 32 + (sub >> 1) * 16);
                const uint32_t sw = SW128(byte);
                ldsm_x4(ah[mt][kt], sb + S_AHI + sw);
                ldsm_x4(al[mt][kt], sb + S_ALO + sw);
            }
        }
    }

    // ---- N chunks of 96 cols (8 batches) ----
    for (int c = 0; c < NCHUNK; c++) {
        __syncthreads();   // previous chunk's fold readers done (no-op cost first iter)

        float acc[2][6][4] = {};
        // B frag address helper (lanes 0..15 meaningful)
        const int bsub = (lane >> 3) & 1;
        const int brin = lane & 7;

        #pragma unroll
        for (int nt = 0; nt < 6; nt++) {
            const int n0 = c * 96 + warp_n * 48 + nt * 8;
            #pragma unroll
            for (int kt = 0; kt < 4; kt++) {
                const uint32_t byte = (uint32_t)((n0 + brin) * 128 + kt * 32 + bsub * 16);
                const uint32_t sw = SW128(byte);
                uint32_t bh0, bh1, bl0, bl1;
                ldsm_x2(bh0, bh1, sb + S_BHI + sw);
                ldsm_x2(bl0, bl1, sb + S_BLO + sw);
                #pragma unroll
                for (int mt = 0; mt < 2; mt++) {
                    mma_bf16(acc[mt][nt], ah[mt][kt], bh0, bh1);  // hi*hi
                    mma_bf16(acc[mt][nt], al[mt][kt], bh0, bh1);  // lo*hi
                    mma_bf16(acc[mt][nt], ah[mt][kt], bl0, bl1);  // hi*lo
                }
            }
        }

        // ---- Store C chunk to smem [128][CPAD] f32 ----
        {
            const int rg = lane >> 2;          // row in group
            const int cc0 = (lane & 3) * 2;    // col pair base
            #pragma unroll
            for (int mt = 0; mt < 2; mt++) {
                #pragma unroll
                for (int nt = 0; nt < 6; nt++) {
                    const int col = warp_n * 48 + nt * 8 + cc0;
                    const int row0 = warp_m * 32 + mt * 16 + rg;
                    float2* p0 = reinterpret_cast<float2*>(
                        smem + S_C + (size_t)row0 * CPAD * 4 + col * 4);
                    p0->x = acc[mt][nt][0]; p0->y = acc[mt][nt][1];
                    float2* p1 = reinterpret_cast<float2*>(
                        smem + S_C + (size_t)(row0 + 8) * CPAD * 4 + col * 4);
                    p1->x = acc[mt][nt][2]; p1->y = acc[mt][nt][3];
                }
            }
        }
        __syncthreads();

        // ---- Fold + store: 128 v x 8 batches of this chunk ----
        #pragma unroll
        for (int i = 0; i < 4; i++) {
            const int item = tid + i * THREADS;     // 0..1023
            const int bl = item >> 7;               // 0..7 batch-local
            const int r = item & 127;               // vertex-local
            const int b = c * 8 + bl;
            const int v = vbase + r;
            const int vc = (v < V) ? v : (V - 1);
            const float x = verts[(size_t)vc * 3 + 0];
            const float y = verts[(size_t)vc * 3 + 1];
            const float z = verts[(size_t)vc * 3 + 2];
            const char* crow = smem + S_C + (size_t)r * CPAD * 4 + bl * 48;
            float4 q0 = *reinterpret_cast<const float4*>(crow);        // e0..3
            float4 q1 = *reinterpret_cast<const float4*>(crow + 16);   // e4..7
            float4 q2 = *reinterpret_cast<const float4*>(crow + 32);   // e8..11
            if (v < V) {
                float o0 = fmaf(q0.x, x, fmaf(q0.y, y, fmaf(q0.z, z, q0.w)));
                float o1 = fmaf(q1.x, x, fmaf(q1.y, y, fmaf(q1.z, z, q1.w)));
                float o2 = fmaf(q2.x, x, fmaf(q2.y, y, fmaf(q2.z, z, q2.w)));
                float* op = out + ((size_t)b * V + v) * 3;
                op[0] = o0; op[1] = o1; op[2] = o2;
            }
        }
    }
}

extern "C" void kernel_launch(void* const* d_in, const int* in_sizes, int n_in,
                              void* d_out, int out_size) {
    const float* verts = (const float*)d_in[0];   // [1,V,3]
    const float* W     = (const float*)d_in[1];   // [1,V,NJ]
    const float* M     = (const float*)d_in[2];   // [NB,NJ,4,4]
    float* out         = (float*)d_out;           // [NB,V,3]

    const int V = in_sizes[0] / 3;

    cudaFuncSetAttribute(skin_mma_kernel,
                         cudaFuncAttributeMaxDynamicSharedMemorySize, S_TOTAL);

    const int grid = (V + MT - 1) / MT;
    skin_mma_kernel<<<grid, THREADS, S_TOTAL>>>(verts, W, M, out, V);
}

// round 9
// speedup vs baseline: 1.9741x; 1.9741x over previous
#include <cuda_runtime.h>
#include <cuda_bf16.h>
#include <cstdint>

// Problem constants
#define NJ 52
#define NB 32
#define KP 64            // K padded (bf16 row = 128 B = SW128 atom)
#define MT 128           // vertices per CTA (GEMM M tile)
#define NTOT 384         // 32 batches * 12 elements, n = b*12 + e
#define NTG 48           // n-tiles of 8
#define THREADS 256      // 8 warps: 4 (M) x 2 (N)
#define NCHUNK 4         // N chunks of 96 cols (8 batches each)
#define CPAD 100         // C smem row stride in floats

// Main-kernel SMEM (dynamic)
#define S_AHI 0
#define S_ALO (S_AHI + MT * 128)          // 16384
#define S_C   (S_ALO + MT * 128)          // 32768
#define S_TOTAL (S_C + MT * CPAD * 4)     // 83968

#define SW128(b) ((b) ^ (((b) >> 3) & 0x70))

// B fragments in final mma layout: [ntg][kt][lane] -> uint2 {b0,b1}
__device__ __align__(16) uint2 g_BfH[NTG * 4 * 32];
__device__ __align__(16) uint2 g_BfL[NTG * 4 * 32];

__device__ __forceinline__ uint32_t smem_u32(const void* p) {
    uint32_t a;
    asm("{ .reg .u64 t; cvta.to.shared.u64 t, %1; cvt.u32.u64 %0, t; }"
        : "=r"(a) : "l"(p));
    return a;
}

__device__ __forceinline__ void ldsm_x4(uint32_t* d, uint32_t addr) {
    asm volatile("ldmatrix.sync.aligned.m8n8.x4.shared.b16 {%0,%1,%2,%3}, [%4];"
                 : "=r"(d[0]), "=r"(d[1]), "=r"(d[2]), "=r"(d[3]) : "r"(addr));
}

__device__ __forceinline__ void ldsm_x2(uint32_t& d0, uint32_t& d1, uint32_t addr) {
    asm volatile("ldmatrix.sync.aligned.m8n8.x2.shared.b16 {%0,%1}, [%2];"
                 : "=r"(d0), "=r"(d1) : "r"(addr));
}

__device__ __forceinline__ void mma_bf16(float* c, const uint32_t* a,
                                         uint32_t b0, uint32_t b1) {
    asm volatile(
        "mma.sync.aligned.m16n8k16.row.col.f32.bf16.bf16.f32 "
        "{%0,%1,%2,%3}, {%4,%5,%6,%7}, {%8,%9}, {%0,%1,%2,%3};"
        : "+f"(c[0]), "+f"(c[1]), "+f"(c[2]), "+f"(c[3])
        : "r"(a[0]), "r"(a[1]), "r"(a[2]), "r"(a[3]), "r"(b0), "r"(b1));
}

__device__ __forceinline__ void split_bf16(float x, __nv_bfloat16& hi, __nv_bfloat16& lo) {
    hi = __float2bfloat16(x);
    lo = __float2bfloat16(x - __bfloat162float(hi));
}

// ---------------- Prep kernel: build B fragments once (48 CTAs) -------------
// CTA t handles n-tile ntg=t (8 n-rows). Fills a tiny swizzled smem image via
// the validated fill path, then warp 0 ldsm's fragments and dumps to global.
__global__ void __launch_bounds__(THREADS)
prep_B_kernel(const float* __restrict__ M) {
    __shared__ __align__(128) char pb[2 * 8 * 128];   // [hi|lo] 8 rows x 128B
    const int tid = threadIdx.x;
    const int lane = tid & 31;
    const int ntg = blockIdx.x;

    if (tid < 8 * 32) {                 // one (row, col-pair) per thread
        const int nl = tid >> 5;        // local n row 0..7
        const int jp = tid & 31;
        const int n = ntg * 8 + nl;
        const int b = n / 12;
        const int e = n - b * 12;
        const int j0 = 2 * jp, j1 = 2 * jp + 1;
        float m0 = (j0 < NJ) ? M[((size_t)b * NJ + j0) * 16 + e] : 0.0f;
        float m1 = (j1 < NJ) ? M[((size_t)b * NJ + j1) * 16 + e] : 0.0f;
        __nv_bfloat16 h0, l0, h1, l1;
        split_bf16(m0, h0, l0);
        split_bf16(m1, h1, l1);
        uint32_t off = SW128((uint32_t)(nl * 128 + jp * 4));
        __nv_bfloat162 hp; hp.x = h0; hp.y = h1;
        __nv_bfloat162 lp; lp.x = l0; lp.y = l1;
        *reinterpret_cast<__nv_bfloat162*>(pb + off) = hp;
        *reinterpret_cast<__nv_bfloat162*>(pb + 1024 + off) = lp;
    }
    __syncthreads();

    if (tid < 32) {
        const uint32_t sbp = smem_u32(pb);
        const int bsub = (lane >> 3) & 1;
        const int brin = lane & 7;
        #pragma unroll
        for (int kt = 0; kt < 4; kt++) {
            const uint32_t byte = (uint32_t)(brin * 128 + kt * 32 + bsub * 16);
            const uint32_t sw = SW128(byte);
            uint32_t h0, h1, l0, l1;
            ldsm_x2(h0, h1, sbp + sw);
            ldsm_x2(l0, l1, sbp + 1024 + sw);
            g_BfH[(ntg * 4 + kt) * 32 + lane] = make_uint2(h0, h1);
            g_BfL[(ntg * 4 + kt) * 32 + lane] = make_uint2(l0, l1);
        }
    }
}

// ---------------- Main kernel ----------------------------------------------
__global__ void __launch_bounds__(THREADS, 2)
skin_mma_kernel(const float* __restrict__ verts,   // [V,3]
                const float* __restrict__ W,       // [V,NJ]
                float* __restrict__ out,           // [NB,V,3]
                int V) {
    extern __shared__ char smem[];
    const uint32_t sb = smem_u32(smem);
    const int tid = threadIdx.x;
    const int lane = tid & 31;
    const int wid = tid >> 5;
    const int warp_m = wid >> 1;     // 0..3
    const int warp_n = wid & 1;      // 0..1
    const int vbase = blockIdx.x * MT;

    // ---- Zero A region (hi+lo, 32KB) ----
    {
        uint4 z = make_uint4(0, 0, 0, 0);
        uint4* p = reinterpret_cast<uint4*>(smem + S_AHI);
        for (int i = tid; i < (2 * MT * 128) / 16; i += THREADS) p[i] = z;
    }
    __syncthreads();

    // ---- Coalesced A fill: W block is contiguous 128*52 floats = 1664 uint4 ----
    {
        const uint4* wp4 = reinterpret_cast<const uint4*>(W + (size_t)vbase * NJ);
        const int lim4 = (V - vbase) * (NJ / 4);   // valid uint4 count in block
        for (int i = tid; i < MT * (NJ / 4); i += THREADS) {
            uint4 raw = (i < lim4) ? wp4[i] : make_uint4(0, 0, 0, 0);
            const int r = i / (NJ / 4);
            const int q = i - r * (NJ / 4);
            const float* f = reinterpret_cast<const float*>(&raw);
            __nv_bfloat16 h[4], l[4];
            #pragma unroll
            for (int u = 0; u < 4; u++) split_bf16(f[u], h[u], l[u]);
            uint32_t hp0, hp1, lp0, lp1;
            {
                __nv_bfloat162 t;
                t.x = h[0]; t.y = h[1]; hp0 = *reinterpret_cast<uint32_t*>(&t);
                t.x = h[2]; t.y = h[3]; hp1 = *reinterpret_cast<uint32_t*>(&t);
                t.x = l[0]; t.y = l[1]; lp0 = *reinterpret_cast<uint32_t*>(&t);
                t.x = l[2]; t.y = l[3]; lp1 = *reinterpret_cast<uint32_t*>(&t);
            }
            const uint32_t off = SW128((uint32_t)(r * 128 + q * 8));  // 8B-aligned
            *reinterpret_cast<uint2*>(smem + S_AHI + off) = make_uint2(hp0, hp1);
            *reinterpret_cast<uint2*>(smem + S_ALO + off) = make_uint2(lp0, lp1);
        }
    }
    __syncthreads();

    // ---- A-hi fragments persistent; base addresses for both arrays ----
    uint32_t ah[2][4][4];
    uint32_t aBaseHi[2], aBaseLo[2];
    {
        const int sub = lane >> 3;
        const int rin = lane & 7;
        #pragma unroll
        for (int mt = 0; mt < 2; mt++) {
            const int row = warp_m * 32 + mt * 16 + rin + (sub & 1) * 8;
            const uint32_t byte = (uint32_t)(row * 128 + (sub >> 1) * 16);
            const uint32_t sw = SW128(byte);   // bits 5-6 of byte are 0 -> kt via XOR
            aBaseHi[mt] = sb + S_AHI + sw;
            aBaseLo[mt] = sb + S_ALO + sw;
            #pragma unroll
            for (int kt = 0; kt < 4; kt++)
                ldsm_x4(ah[mt][kt], aBaseHi[mt] ^ (uint32_t)(kt * 32));
        }
    }

    // ---- N chunks of 96 cols (8 batches each) ----
    for (int c = 0; c < NCHUNK; c++) {
        __syncthreads();   // fold readers of previous chunk done

        float acc[2][6][4] = {};

        #pragma unroll
        for (int kt = 0; kt < 4; kt++) {
            uint32_t al0[4], al1[4];
            ldsm_x4(al0, aBaseLo[0] ^ (uint32_t)(kt * 32));
            ldsm_x4(al1, aBaseLo[1] ^ (uint32_t)(kt * 32));
            #pragma unroll
            for (int nt = 0; nt < 6; nt++) {
                const int ntg = c * 12 + warp_n * 6 + nt;
                const uint2 bh = g_BfH[(ntg * 4 + kt) * 32 + lane];
                const uint2 bl = g_BfL[(ntg * 4 + kt) * 32 + lane];
                mma_bf16(acc[0][nt], ah[0][kt], bh.x, bh.y);   // hi*hi
                mma_bf16(acc[1][nt], ah[1][kt], bh.x, bh.y);
                mma_bf16(acc[0][nt], al0, bh.x, bh.y);         // lo*hi
                mma_bf16(acc[1][nt], al1, bh.x, bh.y);
                mma_bf16(acc[0][nt], ah[0][kt], bl.x, bl.y);   // hi*lo
                mma_bf16(acc[1][nt], ah[1][kt], bl.x, bl.y);
            }
        }

        // ---- Store C chunk to smem [128][CPAD] f32 ----
        {
            const int rg = lane >> 2;
            const int cc0 = (lane & 3) * 2;
            #pragma unroll
            for (int mt = 0; mt < 2; mt++) {
                #pragma unroll
                for (int nt = 0; nt < 6; nt++) {
                    const int col = warp_n * 48 + nt * 8 + cc0;
                    const int row0 = warp_m * 32 + mt * 16 + rg;
                    float2* p0 = reinterpret_cast<float2*>(
                        smem + S_C + (size_t)row0 * CPAD * 4 + col * 4);
                    p0->x = acc[mt][nt][0]; p0->y = acc[mt][nt][1];
                    float2* p1 = reinterpret_cast<float2*>(
                        smem + S_C + (size_t)(row0 + 8) * CPAD * 4 + col * 4);
                    p1->x = acc[mt][nt][2]; p1->y = acc[mt][nt][3];
                }
            }
        }
        __syncthreads();

        // ---- Fold + store: 128 v x 8 batches of this chunk ----
        #pragma unroll
        for (int i = 0; i < 4; i++) {
            const int item = tid + i * THREADS;     // 0..1023
            const int bl = item >> 7;               // 0..7 batch-local
            const int r = item & 127;               // vertex-local
            const int b = c * 8 + bl;
            const int v = vbase + r;
            if (v < V) {
                const float x = verts[(size_t)v * 3 + 0];
                const float y = verts[(size_t)v * 3 + 1];
                const float z = verts[(size_t)v * 3 + 2];
                const char* crow = smem + S_C + (size_t)r * CPAD * 4 + bl * 48;
                float4 q0 = *reinterpret_cast<const float4*>(crow);        // e0..3
                float4 q1 = *reinterpret_cast<const float4*>(crow + 16);   // e4..7
                float4 q2 = *reinterpret_cast<const float4*>(crow + 32);   // e8..11
                float o0 = fmaf(q0.x, x, fmaf(q0.y, y, fmaf(q0.z, z, q0.w)));
                float o1 = fmaf(q1.x, x, fmaf(q1.y, y, fmaf(q1.z, z, q1.w)));
                float o2 = fmaf(q2.x, x, fmaf(q2.y, y, fmaf(q2.z, z, q2.w)));
                float* op = out + ((size_t)b * V + v) * 3;
                op[0] = o0; op[1] = o1; op[2] = o2;
            }
        }
    }
}

extern "C" void kernel_launch(void* const* d_in, const int* in_sizes, int n_in,
                              void* d_out, int out_size) {
    const float* verts = (const float*)d_in[0];   // [1,V,3]
    const float* W     = (const float*)d_in[1];   // [1,V,NJ]
    const float* M     = (const float*)d_in[2];   // [NB,NJ,4,4]
    float* out         = (float*)d_out;           // [NB,V,3]

    const int V = in_sizes[0] / 3;

    cudaFuncSetAttribute(skin_mma_kernel,
                         cudaFuncAttributeMaxDynamicSharedMemorySize, S_TOTAL);

    prep_B_kernel<<<NTG, THREADS>>>(M);

    const int grid = (V + MT - 1) / MT;
    skin_mma_kernel<<<grid, THREADS, S_TOTAL>>>(verts, W, out, V);
}

// round 10
// speedup vs baseline: 2.1047x; 1.0662x over previous
#include <cuda_runtime.h>
#include <cuda_bf16.h>
#include <cstdint>

// Problem constants
#define NJ 52
#define NB 32
#define MT 128           // vertices per CTA (GEMM M tile)
#define NTOT 384         // 32 batches * 12 elements, n = b*12 + e
#define NTG 48           // n-tiles of 8
#define THREADS 256      // 8 warps: 4 (M) x 2 (N)
#define NCHUNK 4         // N chunks of 96 cols (8 batches each)
#define CPAD 100         // C smem row stride in floats

// Main-kernel SMEM (dynamic)
#define S_AHI 0
#define S_ALO (S_AHI + MT * 128)          // 16384
#define S_C   (S_ALO + MT * 128)          // 32768
#define S_TOTAL (S_C + MT * CPAD * 4)     // 83968

#define SW128(b) ((b) ^ (((b) >> 3) & 0x70))

// B fragments, hi/lo interleaved: [ntg][kt][lane] -> uint4 {bh0,bh1,bl0,bl1}
__device__ __align__(16) uint4 g_Bf[NTG * 4 * 32];

__device__ __forceinline__ uint32_t smem_u32(const void* p) {
    uint32_t a;
    asm("{ .reg .u64 t; cvta.to.shared.u64 t, %1; cvt.u32.u64 %0, t; }"
        : "=r"(a) : "l"(p));
    return a;
}

__device__ __forceinline__ void ldsm_x4(uint32_t* d, uint32_t addr) {
    asm volatile("ldmatrix.sync.aligned.m8n8.x4.shared.b16 {%0,%1,%2,%3}, [%4];"
                 : "=r"(d[0]), "=r"(d[1]), "=r"(d[2]), "=r"(d[3]) : "r"(addr));
}

__device__ __forceinline__ void ldsm_x2(uint32_t& d0, uint32_t& d1, uint32_t addr) {
    asm volatile("ldmatrix.sync.aligned.m8n8.x2.shared.b16 {%0,%1}, [%2];"
                 : "=r"(d0), "=r"(d1) : "r"(addr));
}

__device__ __forceinline__ void mma_bf16(float* c, const uint32_t* a,
                                         uint32_t b0, uint32_t b1) {
    asm volatile(
        "mma.sync.aligned.m16n8k16.row.col.f32.bf16.bf16.f32 "
        "{%0,%1,%2,%3}, {%4,%5,%6,%7}, {%8,%9}, {%0,%1,%2,%3};"
        : "+f"(c[0]), "+f"(c[1]), "+f"(c[2]), "+f"(c[3])
        : "r"(a[0]), "r"(a[1]), "r"(a[2]), "r"(a[3]), "r"(b0), "r"(b1));
}

__device__ __forceinline__ void split_bf16(float x, __nv_bfloat16& hi, __nv_bfloat16& lo) {
    hi = __float2bfloat16(x);
    lo = __float2bfloat16(x - __bfloat162float(hi));
}

// ---------------- Prep kernel: build B fragments once (48 CTAs) -------------
__global__ void __launch_bounds__(THREADS)
prep_B_kernel(const float* __restrict__ M) {
    __shared__ __align__(128) char pb[2 * 8 * 128];   // [hi|lo] 8 rows x 128B
    const int tid = threadIdx.x;
    const int lane = tid & 31;
    const int ntg = blockIdx.x;

    if (tid < 8 * 32) {                 // one (row, col-pair) per thread
        const int nl = tid >> 5;        // local n row 0..7
        const int jp = tid & 31;
        const int n = ntg * 8 + nl;
        const int b = n / 12;
        const int e = n - b * 12;
        const int j0 = 2 * jp, j1 = 2 * jp + 1;
        float m0 = (j0 < NJ) ? M[((size_t)b * NJ + j0) * 16 + e] : 0.0f;
        float m1 = (j1 < NJ) ? M[((size_t)b * NJ + j1) * 16 + e] : 0.0f;
        __nv_bfloat16 h0, l0, h1, l1;
        split_bf16(m0, h0, l0);
        split_bf16(m1, h1, l1);
        uint32_t off = SW128((uint32_t)(nl * 128 + jp * 4));
        __nv_bfloat162 hp; hp.x = h0; hp.y = h1;
        __nv_bfloat162 lp; lp.x = l0; lp.y = l1;
        *reinterpret_cast<__nv_bfloat162*>(pb + off) = hp;
        *reinterpret_cast<__nv_bfloat162*>(pb + 1024 + off) = lp;
    }
    __syncthreads();

    if (tid < 32) {
        const uint32_t sbp = smem_u32(pb);
        const int bsub = (lane >> 3) & 1;
        const int brin = lane & 7;
        #pragma unroll
        for (int kt = 0; kt < 4; kt++) {
            const uint32_t byte = (uint32_t)(brin * 128 + kt * 32 + bsub * 16);
            const uint32_t sw = SW128(byte);
            uint32_t h0, h1, l0, l1;
            ldsm_x2(h0, h1, sbp + sw);
            ldsm_x2(l0, l1, sbp + 1024 + sw);
            g_Bf[(ntg * 4 + kt) * 32 + lane] = make_uint4(h0, h1, l0, l1);
        }
    }
}

// ---------------- Main kernel ----------------------------------------------
__global__ void __launch_bounds__(THREADS, 2)
skin_mma_kernel(const float* __restrict__ verts,   // [V,3]
                const float* __restrict__ W,       // [V,NJ]
                float* __restrict__ out,           // [NB,V,3]
                int V) {
    extern __shared__ char smem[];
    const uint32_t sb = smem_u32(smem);
    const int tid = threadIdx.x;
    const int lane = tid & 31;
    const int wid = tid >> 5;
    const int warp_m = wid >> 1;     // 0..3
    const int warp_n = wid & 1;      // 0..1
    const int vbase = blockIdx.x * MT;

    // ---- Zero only the K-pad bytes 104..127 of each A row (hi & lo) ----
    {
        const uint2 z = make_uint2(0, 0);
        for (int i = tid; i < MT * 3 * 2; i += THREADS) {  // 768 uint2
            const int arr = (i >= MT * 3);
            const int k = arr ? (i - MT * 3) : i;
            const int r = k / 3;
            const int q = k - r * 3;
            const uint32_t off = SW128((uint32_t)(r * 128 + 104 + q * 8));
            *reinterpret_cast<uint2*>(smem + (arr ? S_ALO : S_AHI) + off) = z;
        }
    }

    // ---- Coalesced A fill: W block contiguous 128*52 floats = 1664 uint4 ----
    {
        const uint4* wp4 = reinterpret_cast<const uint4*>(W + (size_t)vbase * NJ);
        const int lim4 = (V - vbase) * (NJ / 4);   // valid uint4 count in block
        for (int i = tid; i < MT * (NJ / 4); i += THREADS) {
            uint4 raw = (i < lim4) ? wp4[i] : make_uint4(0, 0, 0, 0);
            const int r = i / (NJ / 4);
            const int q = i - r * (NJ / 4);
            const float* f = reinterpret_cast<const float*>(&raw);
            __nv_bfloat16 h[4], l[4];
            #pragma unroll
            for (int u = 0; u < 4; u++) split_bf16(f[u], h[u], l[u]);
            uint32_t hp0, hp1, lp0, lp1;
            {
                __nv_bfloat162 t;
                t.x = h[0]; t.y = h[1]; hp0 = *reinterpret_cast<uint32_t*>(&t);
                t.x = h[2]; t.y = h[3]; hp1 = *reinterpret_cast<uint32_t*>(&t);
                t.x = l[0]; t.y = l[1]; lp0 = *reinterpret_cast<uint32_t*>(&t);
                t.x = l[2]; t.y = l[3]; lp1 = *reinterpret_cast<uint32_t*>(&t);
            }
            const uint32_t off = SW128((uint32_t)(r * 128 + q * 8));  // 8B-aligned
            *reinterpret_cast<uint2*>(smem + S_AHI + off) = make_uint2(hp0, hp1);
            *reinterpret_cast<uint2*>(smem + S_ALO + off) = make_uint2(lp0, lp1);
        }
    }
    __syncthreads();

    // ---- A-hi fragments persistent; A-lo reloaded per kt via base addr ----
    uint32_t ah[2][4][4];
    uint32_t aBaseLo[2];
    {
        const int sub = lane >> 3;
        const int rin = lane & 7;
        #pragma unroll
        for (int mt = 0; mt < 2; mt++) {
            const int row = warp_m * 32 + mt * 16 + rin + (sub & 1) * 8;
            const uint32_t byte = (uint32_t)(row * 128 + (sub >> 1) * 16);
            const uint32_t sw = SW128(byte);   // byte bits 5-6 are 0 -> kt via XOR
            const uint32_t baseHi = sb + S_AHI + sw;
            aBaseLo[mt] = sb + S_ALO + sw;
            #pragma unroll
            for (int kt = 0; kt < 4; kt++)
                ldsm_x4(ah[mt][kt], baseHi ^ (uint32_t)(kt * 32));
        }
    }

    // ---- N chunks of 96 cols (8 batches each) ----
    // Structure per chunk: mma(c) | sync | storeC(c) | sync | fold(c)
    // fold(c) and mma(c+1) share a sync-free region -> intra-CTA overlap.
    for (int c = 0; c < NCHUNK; c++) {
        float acc[2][6][4] = {};

        #pragma unroll
        for (int kt = 0; kt < 4; kt++) {
            uint32_t al0[4], al1[4];
            ldsm_x4(al0, aBaseLo[0] ^ (uint32_t)(kt * 32));
            ldsm_x4(al1, aBaseLo[1] ^ (uint32_t)(kt * 32));
            #pragma unroll
            for (int nt = 0; nt < 6; nt++) {
                const int ntg = c * 12 + warp_n * 6 + nt;
                const uint4 b = g_Bf[(ntg * 4 + kt) * 32 + lane];
                mma_bf16(acc[0][nt], ah[0][kt], b.x, b.y);   // hi*hi
                mma_bf16(acc[1][nt], ah[1][kt], b.x, b.y);
                mma_bf16(acc[0][nt], al0, b.x, b.y);         // lo*hi
                mma_bf16(acc[1][nt], al1, b.x, b.y);
                mma_bf16(acc[0][nt], ah[0][kt], b.z, b.w);   // hi*lo
                mma_bf16(acc[1][nt], ah[1][kt], b.z, b.w);
            }
        }

        __syncthreads();   // fold readers of chunk c-1 are done with C

        // ---- Store C chunk to smem [128][CPAD] f32 ----
        {
            const int rg = lane >> 2;
            const int cc0 = (lane & 3) * 2;
            #pragma unroll
            for (int mt = 0; mt < 2; mt++) {
                #pragma unroll
                for (int nt = 0; nt < 6; nt++) {
                    const int col = warp_n * 48 + nt * 8 + cc0;
                    const int row0 = warp_m * 32 + mt * 16 + rg;
                    float2* p0 = reinterpret_cast<float2*>(
                        smem + S_C + (size_t)row0 * CPAD * 4 + col * 4);
                    p0->x = acc[mt][nt][0]; p0->y = acc[mt][nt][1];
                    float2* p1 = reinterpret_cast<float2*>(
                        smem + S_C + (size_t)(row0 + 8) * CPAD * 4 + col * 4);
                    p1->x = acc[mt][nt][2]; p1->y = acc[mt][nt][3];
                }
            }
        }
        __syncthreads();

        // ---- Fold + store: 128 v x 8 batches of this chunk ----
        #pragma unroll
        for (int i = 0; i < 4; i++) {
            const int item = tid + i * THREADS;     // 0..1023
            const int bl = item >> 7;               // 0..7 batch-local
            const int r = item & 127;               // vertex-local
            const int b = c * 8 + bl;
            const int v = vbase + r;
            if (v < V) {
                const float x = verts[(size_t)v * 3 + 0];
                const float y = verts[(size_t)v * 3 + 1];
                const float z = verts[(size_t)v * 3 + 2];
                const char* crow = smem + S_C + (size_t)r * CPAD * 4 + bl * 48;
                float4 q0 = *reinterpret_cast<const float4*>(crow);        // e0..3
                float4 q1 = *reinterpret_cast<const float4*>(crow + 16);   // e4..7
                float4 q2 = *reinterpret_cast<const float4*>(crow + 32);   // e8..11
                float o0 = fmaf(q0.x, x, fmaf(q0.y, y, fmaf(q0.z, z, q0.w)));
                float o1 = fmaf(q1.x, x, fmaf(q1.y, y, fmaf(q1.z, z, q1.w)));
                float o2 = fmaf(q2.x, x, fmaf(q2.y, y, fmaf(q2.z, z, q2.w)));
                float* op = out + ((size_t)b * V + v) * 3;
                op[0] = o0; op[1] = o1; op[2] = o2;
            }
        }
    }
}

extern "C" void kernel_launch(void* const* d_in, const int* in_sizes, int n_in,
                              void* d_out, int out_size) {
    const float* verts = (const float*)d_in[0];   // [1,V,3]
    const float* W     = (const float*)d_in[1];   // [1,V,NJ]
    const float* M     = (const float*)d_in[2];   // [NB,NJ,4,4]
    float* out         = (float*)d_out;           // [NB,V,3]

    const int V = in_sizes[0] / 3;

    cudaFuncSetAttribute(skin_mma_kernel,
                         cudaFuncAttributeMaxDynamicSharedMemorySize, S_TOTAL);

    prep_B_kernel<<<NTG, THREADS>>>(M);

    const int grid = (V + MT - 1) / MT;
    skin_mma_kernel<<<grid, THREADS, S_TOTAL>>>(verts, W, out, V);
}

// round 11
// speedup vs baseline: 2.1571x; 1.0249x over previous
#include <cuda_runtime.h>
#include <cuda_bf16.h>
#include <cstdint>

// Problem constants
#define NJ 52
#define NB 32
#define MT 128           // vertices per CTA (GEMM M tile)
#define NTOT 384         // 32 batches * 12 elements, n = b*12 + e
#define NTG 48           // n-tiles of 8
#define THREADS 256      // 8 warps: 4 (M) x 2 (N)
#define NCHUNK 4         // N chunks of 96 cols (8 batches each)
#define CPAD 100         // C smem row stride in floats

// Main-kernel SMEM (dynamic)
#define S_AHI 0
#define S_ALO (S_AHI + MT * 128)          // 16384
#define S_C   (S_ALO + MT * 128)          // 32768
#define S_TOTAL (S_C + MT * CPAD * 4)     // 83968

#define SW128(b) ((b) ^ (((b) >> 3) & 0x70))

// B fragments, hi/lo interleaved: [ntg][kt][lane] -> uint4 {bh0,bh1,bl0,bl1}
__device__ __align__(16) uint4 g_Bf[NTG * 4 * 32];

__device__ __forceinline__ uint32_t smem_u32(const void* p) {
    uint32_t a;
    asm("{ .reg .u64 t; cvta.to.shared.u64 t, %1; cvt.u32.u64 %0, t; }"
        : "=r"(a) : "l"(p));
    return a;
}

__device__ __forceinline__ void ldsm_x4(uint32_t* d, uint32_t addr) {
    asm volatile("ldmatrix.sync.aligned.m8n8.x4.shared.b16 {%0,%1,%2,%3}, [%4];"
                 : "=r"(d[0]), "=r"(d[1]), "=r"(d[2]), "=r"(d[3]) : "r"(addr));
}

__device__ __forceinline__ void ldsm_x2(uint32_t& d0, uint32_t& d1, uint32_t addr) {
    asm volatile("ldmatrix.sync.aligned.m8n8.x2.shared.b16 {%0,%1}, [%2];"
                 : "=r"(d0), "=r"(d1) : "r"(addr));
}

__device__ __forceinline__ void mma_bf16(float* c, const uint32_t* a,
                                         uint32_t b0, uint32_t b1) {
    asm volatile(
        "mma.sync.aligned.m16n8k16.row.col.f32.bf16.bf16.f32 "
        "{%0,%1,%2,%3}, {%4,%5,%6,%7}, {%8,%9}, {%0,%1,%2,%3};"
        : "+f"(c[0]), "+f"(c[1]), "+f"(c[2]), "+f"(c[3])
        : "r"(a[0]), "r"(a[1]), "r"(a[2]), "r"(a[3]), "r"(b0), "r"(b1));
}

__device__ __forceinline__ void split_bf16(float x, __nv_bfloat16& hi, __nv_bfloat16& lo) {
    hi = __float2bfloat16(x);
    lo = __float2bfloat16(x - __bfloat162float(hi));
}

// ---------------- Prep kernel: build B fragments once (48 CTAs) -------------
__global__ void __launch_bounds__(THREADS)
prep_B_kernel(const float* __restrict__ M) {
    __shared__ __align__(128) char pb[2 * 8 * 128];   // [hi|lo] 8 rows x 128B
    const int tid = threadIdx.x;
    const int lane = tid & 31;
    const int ntg = blockIdx.x;

    if (tid < 8 * 32) {                 // one (row, col-pair) per thread
        const int nl = tid >> 5;        // local n row 0..7
        const int jp = tid & 31;
        const int n = ntg * 8 + nl;
        const int b = n / 12;
        const int e = n - b * 12;
        const int j0 = 2 * jp, j1 = 2 * jp + 1;
        float m0 = (j0 < NJ) ? M[((size_t)b * NJ + j0) * 16 + e] : 0.0f;
        float m1 = (j1 < NJ) ? M[((size_t)b * NJ + j1) * 16 + e] : 0.0f;
        __nv_bfloat16 h0, l0, h1, l1;
        split_bf16(m0, h0, l0);
        split_bf16(m1, h1, l1);
        uint32_t off = SW128((uint32_t)(nl * 128 + jp * 4));
        __nv_bfloat162 hp; hp.x = h0; hp.y = h1;
        __nv_bfloat162 lp; lp.x = l0; lp.y = l1;
        *reinterpret_cast<__nv_bfloat162*>(pb + off) = hp;
        *reinterpret_cast<__nv_bfloat162*>(pb + 1024 + off) = lp;
    }
    __syncthreads();

    if (tid < 32) {
        const uint32_t sbp = smem_u32(pb);
        const int bsub = (lane >> 3) & 1;
        const int brin = lane & 7;
        #pragma unroll
        for (int kt = 0; kt < 4; kt++) {
            const uint32_t byte = (uint32_t)(brin * 128 + kt * 32 + bsub * 16);
            const uint32_t sw = SW128(byte);
            uint32_t h0, h1, l0, l1;
            ldsm_x2(h0, h1, sbp + sw);
            ldsm_x2(l0, l1, sbp + 1024 + sw);
            g_Bf[(ntg * 4 + kt) * 32 + lane] = make_uint4(h0, h1, l0, l1);
        }
    }
}

// ---------------- Main kernel ----------------------------------------------
__global__ void __launch_bounds__(THREADS, 2)
skin_mma_kernel(const float* __restrict__ verts,   // [V,3]
                const float* __restrict__ W,       // [V,NJ]
                float* __restrict__ out,           // [NB,V,3]
                int V) {
    extern __shared__ char smem[];
    const uint32_t sb = smem_u32(smem);
    const int tid = threadIdx.x;
    const int lane = tid & 31;
    const int wid = tid >> 5;
    const int warp_m = wid >> 1;     // 0..3
    const int warp_n = wid & 1;      // 0..1
    const int vbase = blockIdx.x * MT;

    // ---- Zero only the K-pad bytes 104..127 of each A row (hi & lo) ----
    {
        const uint2 z = make_uint2(0, 0);
        for (int i = tid; i < MT * 3 * 2; i += THREADS) {  // 768 uint2
            const int arr = (i >= MT * 3);
            const int k = arr ? (i - MT * 3) : i;
            const int r = k / 3;
            const int q = k - r * 3;
            const uint32_t off = SW128((uint32_t)(r * 128 + 104 + q * 8));
            *reinterpret_cast<uint2*>(smem + (arr ? S_ALO : S_AHI) + off) = z;
        }
    }

    // ---- Coalesced A fill: W block contiguous 128*52 floats = 1664 uint4 ----
    {
        const uint4* wp4 = reinterpret_cast<const uint4*>(W + (size_t)vbase * NJ);
        const int lim4 = (V - vbase) * (NJ / 4);   // valid uint4 count in block
        for (int i = tid; i < MT * (NJ / 4); i += THREADS) {
            uint4 raw = (i < lim4) ? wp4[i] : make_uint4(0, 0, 0, 0);
            const int r = i / (NJ / 4);
            const int q = i - r * (NJ / 4);
            const float* f = reinterpret_cast<const float*>(&raw);
            __nv_bfloat16 h[4], l[4];
            #pragma unroll
            for (int u = 0; u < 4; u++) split_bf16(f[u], h[u], l[u]);
            uint32_t hp0, hp1, lp0, lp1;
            {
                __nv_bfloat162 t;
                t.x = h[0]; t.y = h[1]; hp0 = *reinterpret_cast<uint32_t*>(&t);
                t.x = h[2]; t.y = h[3]; hp1 = *reinterpret_cast<uint32_t*>(&t);
                t.x = l[0]; t.y = l[1]; lp0 = *reinterpret_cast<uint32_t*>(&t);
                t.x = l[2]; t.y = l[3]; lp1 = *reinterpret_cast<uint32_t*>(&t);
            }
            const uint32_t off = SW128((uint32_t)(r * 128 + q * 8));  // 8B-aligned
            *reinterpret_cast<uint2*>(smem + S_AHI + off) = make_uint2(hp0, hp1);
            *reinterpret_cast<uint2*>(smem + S_ALO + off) = make_uint2(lp0, lp1);
        }
    }
    __syncthreads();

    // ---- A-hi fragments persistent; A-lo reloaded per kt via base addr ----
    uint32_t ah[2][4][4];
    uint32_t aBaseLo[2];
    {
        const int sub = lane >> 3;
        const int rin = lane & 7;
        #pragma unroll
        for (int mt = 0; mt < 2; mt++) {
            const int row = warp_m * 32 + mt * 16 + rin + (sub & 1) * 8;
            const uint32_t byte = (uint32_t)(row * 128 + (sub >> 1) * 16);
            const uint32_t sw = SW128(byte);   // byte bits 5-6 are 0 -> kt via XOR
            const uint32_t baseHi = sb + S_AHI + sw;
            aBaseLo[mt] = sb + S_ALO + sw;
            #pragma unroll
            for (int kt = 0; kt < 4; kt++)
                ldsm_x4(ah[mt][kt], baseHi ^ (uint32_t)(kt * 32));
        }
    }

    // ---- N chunks of 96 cols (8 batches each) ----
    // Structure per chunk: mma(c) | sync | storeC(c) | sync | fold(c)
    // fold(c) and mma(c+1) share a sync-free region -> intra-CTA overlap.
    for (int c = 0; c < NCHUNK; c++) {
        float acc[2][6][4] = {};

        #pragma unroll
        for (int kt = 0; kt < 4; kt++) {
            uint32_t al0[4], al1[4];
            ldsm_x4(al0, aBaseLo[0] ^ (uint32_t)(kt * 32));
            ldsm_x4(al1, aBaseLo[1] ^ (uint32_t)(kt * 32));
            #pragma unroll
            for (int nt = 0; nt < 6; nt++) {
                const int ntg = c * 12 + warp_n * 6 + nt;
                const uint4 b = g_Bf[(ntg * 4 + kt) * 32 + lane];
                mma_bf16(acc[0][nt], ah[0][kt], b.x, b.y);   // hi*hi
                mma_bf16(acc[1][nt], ah[1][kt], b.x, b.y);
                mma_bf16(acc[0][nt], al0, b.x, b.y);         // lo*hi
                mma_bf16(acc[1][nt], al1, b.x, b.y);
                mma_bf16(acc[0][nt], ah[0][kt], b.z, b.w);   // hi*lo
                mma_bf16(acc[1][nt], ah[1][kt], b.z, b.w);
            }
        }

        __syncthreads();   // fold readers of chunk c-1 are done with C

        // ---- Store C chunk to smem [128][CPAD] f32 ----
        {
            const int rg = lane >> 2;
            const int cc0 = (lane & 3) * 2;
            #pragma unroll
            for (int mt = 0; mt < 2; mt++) {
                #pragma unroll
                for (int nt = 0; nt < 6; nt++) {
                    const int col = warp_n * 48 + nt * 8 + cc0;
                    const int row0 = warp_m * 32 + mt * 16 + rg;
                    float2* p0 = reinterpret_cast<float2*>(
                        smem + S_C + (size_t)row0 * CPAD * 4 + col * 4);
                    p0->x = acc[mt][nt][0]; p0->y = acc[mt][nt][1];
                    float2* p1 = reinterpret_cast<float2*>(
                        smem + S_C + (size_t)(row0 + 8) * CPAD * 4 + col * 4);
                    p1->x = acc[mt][nt][2]; p1->y = acc[mt][nt][3];
                }
            }
        }
        __syncthreads();

        // ---- Fold + store: 128 v x 8 batches of this chunk ----
        #pragma unroll
        for (int i = 0; i < 4; i++) {
            const int item = tid + i * THREADS;     // 0..1023
            const int bl = item >> 7;               // 0..7 batch-local
            const int r = item & 127;               // vertex-local
            const int b = c * 8 + bl;
            const int v = vbase + r;
            if (v < V) {
                const float x = verts[(size_t)v * 3 + 0];
                const float y = verts[(size_t)v * 3 + 1];
                const float z = verts[(size_t)v * 3 + 2];
                const char* crow = smem + S_C + (size_t)r * CPAD * 4 + bl * 48;
                float4 q0 = *reinterpret_cast<const float4*>(crow);        // e0..3
                float4 q1 = *reinterpret_cast<const float4*>(crow + 16);   // e4..7
                float4 q2 = *reinterpret_cast<const float4*>(crow + 32);   // e8..11
                float o0 = fmaf(q0.x, x, fmaf(q0.y, y, fmaf(q0.z, z, q0.w)));
                float o1 = fmaf(q1.x, x, fmaf(q1.y, y, fmaf(q1.z, z, q1.w)));
                float o2 = fmaf(q2.x, x, fmaf(q2.y, y, fmaf(q2.z, z, q2.w)));
                float* op = out + ((size_t)b * V + v) * 3;
                op[0] = o0; op[1] = o1; op[2] = o2;
            }
        }
    }
}

extern "C" void kernel_launch(void* const* d_in, const int* in_sizes, int n_in,
                              void* d_out, int out_size) {
    const float* verts = (const float*)d_in[0];   // [1,V,3]
    const float* W     = (const float*)d_in[1];   // [1,V,NJ]
    const float* M     = (const float*)d_in[2];   // [NB,NJ,4,4]
    float* out         = (float*)d_out;           // [NB,V,3]

    const int V = in_sizes[0] / 3;

    cudaFuncSetAttribute(skin_mma_kernel,
                         cudaFuncAttributeMaxDynamicSharedMemorySize, S_TOTAL);

    prep_B_kernel<<<NTG, THREADS>>>(M);

    const int grid = (V + MT - 1) / MT;
    skin_mma_kernel<<<grid, THREADS, S_TOTAL>>>(verts, W, out, V);
}